// round 1
// baseline (speedup 1.0000x reference)
#include <cuda_runtime.h>
#include <math.h>

#define NB   32
#define NL   2048
#define ND   512
#define NDFF 256
#define NBLK 6
#define FEPS 1e-6f
#define LCHUNK 128
#define NCHUNK (NL / LCHUNK)   // 16

// ---------------- device scratch (no allocations allowed) ----------------
__device__ float g_q[NB * ND];            // evolving query
__device__ float g_scores[NB * NL];       // raw scores
__device__ float g_s[NB * NL];            // softmax probs (contiguous)
__device__ float g_Apart[NB * NCHUNK * ND]; // partial attention outputs

// ---------------- helpers ----------------
__device__ __forceinline__ float block_sum_512(float v, float* red) {
    // full 512-thread block sum with broadcast; red must hold >=16 floats
    #pragma unroll
    for (int o = 16; o; o >>= 1) v += __shfl_xor_sync(0xffffffffu, v, o);
    int w = threadIdx.x >> 5;
    if ((threadIdx.x & 31) == 0) red[w] = v;
    __syncthreads();
    if (threadIdx.x < 16) {
        float t = red[threadIdx.x];
        #pragma unroll
        for (int o = 8; o; o >>= 1) t += __shfl_xor_sync(0xffffu, t, o);
        if (threadIdx.x == 0) red[0] = t;
    }
    __syncthreads();
    float r = red[0];
    __syncthreads();  // safe reuse of red
    return r;
}

// ---------------- kernels ----------------
__global__ void initq_kernel(const float* __restrict__ q) {
    int i = blockIdx.x * blockDim.x + threadIdx.x;
    if (i < NB * ND) g_q[i] = q[i];
}

// scores[b,l] = <q[b,:], k[b,l,:]> / sqrt(D); one warp per (b,l)
__global__ void scores_kernel(const float* __restrict__ k) {
    int warp = (blockIdx.x * blockDim.x + threadIdx.x) >> 5;
    int lane = threadIdx.x & 31;
    if (warp >= NB * NL) return;
    int b = warp >> 11;          // / 2048
    const float4* k4 = reinterpret_cast<const float4*>(k + (size_t)warp * ND);
    const float4* q4 = reinterpret_cast<const float4*>(g_q + b * ND);
    float acc = 0.f;
    #pragma unroll
    for (int i = 0; i < 4; i++) {
        float4 kv = __ldg(&k4[i * 32 + lane]);
        float4 qv = q4[i * 32 + lane];
        acc = fmaf(kv.x, qv.x, acc);
        acc = fmaf(kv.y, qv.y, acc);
        acc = fmaf(kv.z, qv.z, acc);
        acc = fmaf(kv.w, qv.w, acc);
    }
    #pragma unroll
    for (int o = 16; o; o >>= 1) acc += __shfl_xor_sync(0xffffffffu, acc, o);
    if (lane == 0) g_scores[warp] = acc * 0.04419417382415922f;  // 1/sqrt(512)
}

// softmax over L per batch; writes contiguous g_s and strided weights[:, :, blk]
__global__ void softmax_kernel(float* __restrict__ wout, int blk) {
    int b = blockIdx.x;
    int t = threadIdx.x;            // 256 threads
    __shared__ float red[256];
    const float* sc = g_scores + b * NL;

    float m = -INFINITY;
    float e[NL / 256];
    #pragma unroll
    for (int i = 0; i < NL / 256; i++) {
        e[i] = sc[t + i * 256];
        m = fmaxf(m, e[i]);
    }
    red[t] = m; __syncthreads();
    for (int s = 128; s; s >>= 1) {
        if (t < s) red[t] = fmaxf(red[t], red[t + s]);
        __syncthreads();
    }
    m = red[0]; __syncthreads();

    float sum = 0.f;
    #pragma unroll
    for (int i = 0; i < NL / 256; i++) {
        e[i] = expf(e[i] - m);
        sum += e[i];
    }
    red[t] = sum; __syncthreads();
    for (int s = 128; s; s >>= 1) {
        if (t < s) red[t] += red[t + s];
        __syncthreads();
    }
    float inv = 1.0f / red[0];

    #pragma unroll
    for (int i = 0; i < NL / 256; i++) {
        int l = t + i * 256;
        float sv = e[i] * inv;
        g_s[b * NL + l] = sv;
        wout[((size_t)b * NL + l) * NBLK + blk] = sv;
    }
}

// partial A: one block per (l-chunk, b); thread = d; stream V
__global__ void apart_kernel(const float* __restrict__ v) {
    int c = blockIdx.x;     // 0..15
    int b = blockIdx.y;     // 0..31
    int d = threadIdx.x;    // 0..511
    __shared__ float ss[LCHUNK];
    if (d < LCHUNK) ss[d] = g_s[b * NL + c * LCHUNK + d];
    __syncthreads();
    const float* vp = v + ((size_t)b * NL + (size_t)c * LCHUNK) * ND + d;
    float a0 = 0.f, a1 = 0.f, a2 = 0.f, a3 = 0.f;
    #pragma unroll 8
    for (int l = 0; l < LCHUNK; l += 4) {
        a0 = fmaf(ss[l + 0], __ldg(vp + (l + 0) * ND), a0);
        a1 = fmaf(ss[l + 1], __ldg(vp + (l + 1) * ND), a1);
        a2 = fmaf(ss[l + 2], __ldg(vp + (l + 2) * ND), a2);
        a3 = fmaf(ss[l + 3], __ldg(vp + (l + 3) * ND), a3);
    }
    g_Apart[(b * NCHUNK + c) * ND + d] = (a0 + a1) + (a2 + a3);
}

// fused: reduce partials + residual + Norm1 + FF(relu) + FF2 + residual + Norm2
__global__ void tail_kernel(const float* __restrict__ W1, const float* __restrict__ b1,
                            const float* __restrict__ W2, const float* __restrict__ b2,
                            const float* __restrict__ al1, const float* __restrict__ bi1,
                            const float* __restrict__ al2, const float* __restrict__ bi2,
                            float* __restrict__ out, int blk, int write_out, int out_off) {
    int b = blockIdx.x;   // 32
    int d = threadIdx.x;  // 512
    __shared__ float red[16];
    __shared__ float sh_q[ND];
    __shared__ float sh_h[NDFF];

    // 1. A = sum partials, x = A + q
    float x = g_q[b * ND + d];
    #pragma unroll
    for (int c = 0; c < NCHUNK; c++) x += g_Apart[(b * NCHUNK + c) * ND + d];

    // 2. Norm1 (ddof=1, denom std+eps)
    float mu  = block_sum_512(x, red) * (1.0f / ND);
    float dev = x - mu;
    float var = block_sum_512(dev * dev, red) * (1.0f / (ND - 1));
    float qn1 = al1[blk * ND + d] * dev / (sqrtf(var) + FEPS) + bi1[blk * ND + d];
    sh_q[d] = qn1;
    __syncthreads();

    // 3. h = relu(q_ @ W1 + b1): threads 0..255 each own one j
    if (d < NDFF) {
        float acc = b1[blk * NDFF + d];
        const float* w = W1 + (size_t)blk * ND * NDFF + d;  // col d, stride NDFF
        float c0 = 0.f, c1 = 0.f, c2 = 0.f, c3 = 0.f;
        #pragma unroll 4
        for (int i = 0; i < ND; i += 4) {
            c0 = fmaf(sh_q[i + 0], __ldg(w + (i + 0) * NDFF), c0);
            c1 = fmaf(sh_q[i + 1], __ldg(w + (i + 1) * NDFF), c1);
            c2 = fmaf(sh_q[i + 2], __ldg(w + (i + 2) * NDFF), c2);
            c3 = fmaf(sh_q[i + 3], __ldg(w + (i + 3) * NDFF), c3);
        }
        acc += (c0 + c1) + (c2 + c3);
        sh_h[d] = fmaxf(acc, 0.f);
    }
    __syncthreads();

    // 4. ff = h @ W2 + b2
    float acc = b2[blk * ND + d];
    {
        const float* w2 = W2 + (size_t)blk * NDFF * ND + d;  // col d, stride ND
        float c0 = 0.f, c1 = 0.f, c2 = 0.f, c3 = 0.f;
        #pragma unroll 4
        for (int j = 0; j < NDFF; j += 4) {
            c0 = fmaf(sh_h[j + 0], __ldg(w2 + (j + 0) * ND), c0);
            c1 = fmaf(sh_h[j + 1], __ldg(w2 + (j + 1) * ND), c1);
            c2 = fmaf(sh_h[j + 2], __ldg(w2 + (j + 2) * ND), c2);
            c3 = fmaf(sh_h[j + 3], __ldg(w2 + (j + 3) * ND), c3);
        }
        acc += (c0 + c1) + (c2 + c3);
    }
    float x2 = qn1 + acc;

    // 5. Norm2
    float mu2  = block_sum_512(x2, red) * (1.0f / ND);
    float dev2 = x2 - mu2;
    float var2 = block_sum_512(dev2 * dev2, red) * (1.0f / (ND - 1));
    float qn2 = al2[blk * ND + d] * dev2 / (sqrtf(var2) + FEPS) + bi2[blk * ND + d];

    g_q[b * ND + d] = qn2;
    if (write_out) out[b * (2 * ND) + out_off + d] = qn2;
}

// ---------------- launch ----------------
extern "C" void kernel_launch(void* const* d_in, const int* in_sizes, int n_in,
                              void* d_out, int out_size) {
    const float* q   = (const float*)d_in[0];
    const float* k   = (const float*)d_in[1];
    const float* v   = (const float*)d_in[2];
    const float* W1  = (const float*)d_in[3];
    const float* b1  = (const float*)d_in[4];
    const float* W2  = (const float*)d_in[5];
    const float* b2  = (const float*)d_in[6];
    const float* al1 = (const float*)d_in[7];
    const float* bi1 = (const float*)d_in[8];
    const float* al2 = (const float*)d_in[9];
    const float* bi2 = (const float*)d_in[10];

    float* out_p = (float*)d_out;                 // (32, 1024)
    float* w_p   = (float*)d_out + NB * 2 * ND;   // (32, 2048, 6)

    initq_kernel<<<(NB * ND + 255) / 256, 256>>>(q);

    for (int blk = 0; blk < NBLK; blk++) {
        scores_kernel<<<(NB * NL * 32) / 256, 256>>>(k);
        softmax_kernel<<<NB, 256>>>(w_p, blk);
        apart_kernel<<<dim3(NCHUNK, NB), ND>>>(v);
        int wr = (blk == 2 || blk == 5) ? 1 : 0;
        int off = (blk == 5) ? ND : 0;
        tail_kernel<<<NB, ND>>>(W1, b1, W2, b2, al1, bi1, al2, bi2,
                                out_p, blk, wr, off);
    }
}

// round 2
// speedup vs baseline: 1.2287x; 1.2287x over previous
#include <cuda_runtime.h>
#include <math.h>

#define NB   32
#define NL   2048
#define ND   512
#define NDFF 256
#define NBLK 6
#define FEPS 1e-6f
#define LCHUNK 128
#define NCHUNK (NL / LCHUNK)   // 16

// ---------------- device scratch (no allocations allowed) ----------------
__device__ float g_q[NB * ND];              // evolving query
__device__ float g_scores[NB * NL];         // raw scores
__device__ float g_s[NB * NL];              // softmax probs (contiguous)
__device__ float g_Apart[NB * NCHUNK * ND]; // partial attention outputs

// ---------------- helpers ----------------
__device__ __forceinline__ float block_sum_512(float v, float* red) {
    #pragma unroll
    for (int o = 16; o; o >>= 1) v += __shfl_xor_sync(0xffffffffu, v, o);
    int w = threadIdx.x >> 5;
    if ((threadIdx.x & 31) == 0) red[w] = v;
    __syncthreads();
    if (threadIdx.x < 16) {
        float t = red[threadIdx.x];
        #pragma unroll
        for (int o = 8; o; o >>= 1) t += __shfl_xor_sync(0xffffu, t, o);
        if (threadIdx.x == 0) red[0] = t;
    }
    __syncthreads();
    float r = red[0];
    __syncthreads();
    return r;
}

// ---------------- kernels ----------------
__global__ void initq_kernel(const float* __restrict__ q) {
    int i = blockIdx.x * blockDim.x + threadIdx.x;
    if (i < NB * ND) g_q[i] = q[i];
}

// scores[b,l] = <q[b,:], k[b,l,:]> / sqrt(D); one warp per (b,l)
__global__ void scores_kernel(const float* __restrict__ k) {
    int warp = (blockIdx.x * blockDim.x + threadIdx.x) >> 5;
    int lane = threadIdx.x & 31;
    if (warp >= NB * NL) return;
    int b = warp >> 11;          // / 2048
    const float4* k4 = reinterpret_cast<const float4*>(k + (size_t)warp * ND);
    const float4* q4 = reinterpret_cast<const float4*>(g_q + b * ND);
    float acc = 0.f;
    #pragma unroll
    for (int i = 0; i < 4; i++) {
        float4 kv = __ldg(&k4[i * 32 + lane]);
        float4 qv = q4[i * 32 + lane];
        acc = fmaf(kv.x, qv.x, acc);
        acc = fmaf(kv.y, qv.y, acc);
        acc = fmaf(kv.z, qv.z, acc);
        acc = fmaf(kv.w, qv.w, acc);
    }
    #pragma unroll
    for (int o = 16; o; o >>= 1) acc += __shfl_xor_sync(0xffffffffu, acc, o);
    if (lane == 0) g_scores[warp] = acc * 0.04419417382415922f;  // 1/sqrt(512)
}

// softmax over L per batch; writes contiguous g_s and strided weights[:, :, blk]
__global__ void softmax_kernel(float* __restrict__ wout, int blk) {
    int b = blockIdx.x;
    int t = threadIdx.x;            // 512 threads
    __shared__ float red[16];
    const float* sc = g_scores + b * NL;

    float e[NL / 512];
    float m = -INFINITY;
    #pragma unroll
    for (int i = 0; i < NL / 512; i++) {
        e[i] = sc[t + i * 512];
        m = fmaxf(m, e[i]);
    }
    // block max via sum helper pattern (use shfl max)
    #pragma unroll
    for (int o = 16; o; o >>= 1) m = fmaxf(m, __shfl_xor_sync(0xffffffffu, m, o));
    int w = t >> 5;
    if ((t & 31) == 0) red[w] = m;
    __syncthreads();
    if (t < 16) {
        float x = red[t];
        #pragma unroll
        for (int o = 8; o; o >>= 1) x = fmaxf(x, __shfl_xor_sync(0xffffu, x, o));
        if (t == 0) red[0] = x;
    }
    __syncthreads();
    m = red[0];
    __syncthreads();

    float sum = 0.f;
    #pragma unroll
    for (int i = 0; i < NL / 512; i++) {
        e[i] = expf(e[i] - m);
        sum += e[i];
    }
    float tot = block_sum_512(sum, red);
    float inv = 1.0f / tot;

    #pragma unroll
    for (int i = 0; i < NL / 512; i++) {
        int l = t + i * 512;
        float sv = e[i] * inv;
        g_s[b * NL + l] = sv;
        wout[((size_t)b * NL + l) * NBLK + blk] = sv;
    }
}

// partial A: one block per (l-chunk, b); 128 threads, float4 per thread
__global__ void apart_kernel(const float* __restrict__ v) {
    int c = blockIdx.x;     // 0..15
    int b = blockIdx.y;     // 0..31
    int t = threadIdx.x;    // 0..127
    __shared__ float ss[LCHUNK];
    ss[t] = g_s[b * NL + c * LCHUNK + t];
    __syncthreads();
    const float4* vp = reinterpret_cast<const float4*>(
        v + ((size_t)b * NL + (size_t)c * LCHUNK) * ND) + t;  // row stride ND/4=128
    float4 a0 = {0,0,0,0}, a1 = {0,0,0,0}, a2 = {0,0,0,0}, a3 = {0,0,0,0};
    #pragma unroll 4
    for (int l = 0; l < LCHUNK; l += 4) {
        float4 v0 = __ldg(vp + (l + 0) * 128);
        float4 v1 = __ldg(vp + (l + 1) * 128);
        float4 v2 = __ldg(vp + (l + 2) * 128);
        float4 v3 = __ldg(vp + (l + 3) * 128);
        float s0 = ss[l + 0], s1 = ss[l + 1], s2 = ss[l + 2], s3 = ss[l + 3];
        a0.x = fmaf(s0, v0.x, a0.x); a0.y = fmaf(s0, v0.y, a0.y);
        a0.z = fmaf(s0, v0.z, a0.z); a0.w = fmaf(s0, v0.w, a0.w);
        a1.x = fmaf(s1, v1.x, a1.x); a1.y = fmaf(s1, v1.y, a1.y);
        a1.z = fmaf(s1, v1.z, a1.z); a1.w = fmaf(s1, v1.w, a1.w);
        a2.x = fmaf(s2, v2.x, a2.x); a2.y = fmaf(s2, v2.y, a2.y);
        a2.z = fmaf(s2, v2.z, a2.z); a2.w = fmaf(s2, v2.w, a2.w);
        a3.x = fmaf(s3, v3.x, a3.x); a3.y = fmaf(s3, v3.y, a3.y);
        a3.z = fmaf(s3, v3.z, a3.z); a3.w = fmaf(s3, v3.w, a3.w);
    }
    float4 r;
    r.x = (a0.x + a1.x) + (a2.x + a3.x);
    r.y = (a0.y + a1.y) + (a2.y + a3.y);
    r.z = (a0.z + a1.z) + (a2.z + a3.z);
    r.w = (a0.w + a1.w) + (a2.w + a3.w);
    reinterpret_cast<float4*>(g_Apart + (b * NCHUNK + c) * ND)[t] = r;
}

// fused tail: reduce partials + residual + Norm1 + FF(relu) + FF2 + residual + Norm2
__global__ void tail_kernel(const float* __restrict__ W1, const float* __restrict__ b1,
                            const float* __restrict__ W2, const float* __restrict__ b2,
                            const float* __restrict__ al1, const float* __restrict__ bi1,
                            const float* __restrict__ al2, const float* __restrict__ bi2,
                            float* __restrict__ out, int blk, int write_out, int out_off) {
    int b = blockIdx.x;   // 32
    int d = threadIdx.x;  // 512
    __shared__ float red[16];
    __shared__ float sh_q[ND];
    __shared__ float sh_p[ND];     // FF1 partials (2 halves)
    __shared__ float sh_h[NDFF];

    // 1. A = sum partials, x = A + q
    float x = g_q[b * ND + d];
    #pragma unroll
    for (int c = 0; c < NCHUNK; c++) x += g_Apart[(b * NCHUNK + c) * ND + d];

    // 2. Norm1 (ddof=1, denom std+eps)
    float mu  = block_sum_512(x, red) * (1.0f / ND);
    float dev = x - mu;
    float var = block_sum_512(dev * dev, red) * (1.0f / (ND - 1));
    float qn1 = al1[blk * ND + d] * dev / (sqrtf(var) + FEPS) + bi1[blk * ND + d];
    sh_q[d] = qn1;
    __syncthreads();

    // 3. FF1: h = relu(q_ @ W1 + b1). 512 threads: thread = (half, j),
    //    half in {0,1} splits the i-range; high MLP via unroll.
    {
        int j    = d & (NDFF - 1);
        int half = d >> 8;
        const float* w  = W1 + (size_t)blk * ND * NDFF + (size_t)(half * 256) * NDFF + j;
        const float* xq = sh_q + half * 256;
        float c0 = 0.f, c1 = 0.f, c2 = 0.f, c3 = 0.f;
        #pragma unroll 4
        for (int i = 0; i < 256; i += 4) {
            c0 = fmaf(xq[i + 0], __ldg(w + (i + 0) * NDFF), c0);
            c1 = fmaf(xq[i + 1], __ldg(w + (i + 1) * NDFF), c1);
            c2 = fmaf(xq[i + 2], __ldg(w + (i + 2) * NDFF), c2);
            c3 = fmaf(xq[i + 3], __ldg(w + (i + 3) * NDFF), c3);
        }
        sh_p[d] = (c0 + c1) + (c2 + c3);
    }
    __syncthreads();
    if (d < NDFF) {
        float hv = sh_p[d] + sh_p[d + 256] + b1[blk * NDFF + d];
        sh_h[d] = fmaxf(hv, 0.f);
    }
    __syncthreads();

    // 4. FF2: ff = h @ W2 + b2 (512 threads, one output d each, high MLP)
    float acc = b2[blk * ND + d];
    {
        const float* w2 = W2 + (size_t)blk * NDFF * ND + d;  // col d, stride ND
        float c0 = 0.f, c1 = 0.f, c2 = 0.f, c3 = 0.f;
        #pragma unroll 4
        for (int j = 0; j < NDFF; j += 4) {
            c0 = fmaf(sh_h[j + 0], __ldg(w2 + (j + 0) * ND), c0);
            c1 = fmaf(sh_h[j + 1], __ldg(w2 + (j + 1) * ND), c1);
            c2 = fmaf(sh_h[j + 2], __ldg(w2 + (j + 2) * ND), c2);
            c3 = fmaf(sh_h[j + 3], __ldg(w2 + (j + 3) * ND), c3);
        }
        acc += (c0 + c1) + (c2 + c3);
    }
    float x2 = qn1 + acc;

    // 5. Norm2
    float mu2  = block_sum_512(x2, red) * (1.0f / ND);
    float dev2 = x2 - mu2;
    float var2 = block_sum_512(dev2 * dev2, red) * (1.0f / (ND - 1));
    float qn2 = al2[blk * ND + d] * dev2 / (sqrtf(var2) + FEPS) + bi2[blk * ND + d];

    g_q[b * ND + d] = qn2;
    if (write_out) out[b * (2 * ND) + out_off + d] = qn2;
}

// ---------------- launch ----------------
extern "C" void kernel_launch(void* const* d_in, const int* in_sizes, int n_in,
                              void* d_out, int out_size) {
    const float* q   = (const float*)d_in[0];
    const float* k   = (const float*)d_in[1];
    const float* v   = (const float*)d_in[2];
    const float* W1  = (const float*)d_in[3];
    const float* b1  = (const float*)d_in[4];
    const float* W2  = (const float*)d_in[5];
    const float* b2  = (const float*)d_in[6];
    const float* al1 = (const float*)d_in[7];
    const float* bi1 = (const float*)d_in[8];
    const float* al2 = (const float*)d_in[9];
    const float* bi2 = (const float*)d_in[10];

    float* out_p = (float*)d_out;                 // (32, 1024)
    float* w_p   = (float*)d_out + NB * 2 * ND;   // (32, 2048, 6)

    initq_kernel<<<(NB * ND + 255) / 256, 256>>>(q);

    for (int blk = 0; blk < NBLK; blk++) {
        scores_kernel<<<(NB * NL * 32) / 256, 256>>>(k);
        softmax_kernel<<<NB, 512>>>(w_p, blk);
        apart_kernel<<<dim3(NCHUNK, NB), LCHUNK>>>(v);
        int wr = (blk == 2 || blk == 5) ? 1 : 0;
        int off = (blk == 5) ? ND : 0;
        tail_kernel<<<NB, ND>>>(W1, b1, W2, b2, al1, bi1, al2, bi2,
                                out_p, blk, wr, off);
    }
}

// round 3
// speedup vs baseline: 2.2120x; 1.8003x over previous
#include <cuda_runtime.h>
#include <math.h>

#define NB   32
#define NL   2048
#define ND   512
#define NDFF 256
#define NBLK 6
#define FEPS 1e-6f
#define LCHUNK 64
#define NCHUNK (NL / LCHUNK)   // 32

// ---------------- device scratch (no allocations allowed) ----------------
__device__ float g_q[NB * ND];              // evolving query
__device__ float g_scores[NB * NL];         // raw scores
__device__ float g_s[NB * NL];              // softmax probs (contiguous)
__device__ float g_Apart[NB * NCHUNK * ND]; // partial attention outputs

// ---------------- helpers ----------------
__device__ __forceinline__ float block_sum_512(float v, float* red) {
    #pragma unroll
    for (int o = 16; o; o >>= 1) v += __shfl_xor_sync(0xffffffffu, v, o);
    int w = threadIdx.x >> 5;
    if ((threadIdx.x & 31) == 0) red[w] = v;
    __syncthreads();
    if (threadIdx.x < 16) {
        float t = red[threadIdx.x];
        #pragma unroll
        for (int o = 8; o; o >>= 1) t += __shfl_xor_sync(0xffffu, t, o);
        if (threadIdx.x == 0) red[0] = t;
    }
    __syncthreads();
    float r = red[0];
    __syncthreads();
    return r;
}

// ---------------- kernels ----------------
__global__ void initq_kernel(const float* __restrict__ q) {
    int i = blockIdx.x * blockDim.x + threadIdx.x;
    if (i < NB * ND) g_q[i] = q[i];
}

// scores[b,l] = <q[b,:], k[b,l,:]> / sqrt(D); one warp per (b,l)
// loads hoisted ahead of FMAs, streaming hint on K
__global__ void scores_kernel(const float* __restrict__ k) {
    int warp = (blockIdx.x * blockDim.x + threadIdx.x) >> 5;
    int lane = threadIdx.x & 31;
    if (warp >= NB * NL) return;
    int b = warp >> 11;          // / 2048
    const float4* k4 = reinterpret_cast<const float4*>(k + (size_t)warp * ND) + lane;
    const float4* q4 = reinterpret_cast<const float4*>(g_q + b * ND) + lane;

    float4 kv0 = __ldcs(k4 + 0 * 32);
    float4 kv1 = __ldcs(k4 + 1 * 32);
    float4 kv2 = __ldcs(k4 + 2 * 32);
    float4 kv3 = __ldcs(k4 + 3 * 32);
    float4 qv0 = q4[0 * 32];
    float4 qv1 = q4[1 * 32];
    float4 qv2 = q4[2 * 32];
    float4 qv3 = q4[3 * 32];

    float a = 0.f, bacc = 0.f;
    a = fmaf(kv0.x, qv0.x, a); bacc = fmaf(kv0.y, qv0.y, bacc);
    a = fmaf(kv0.z, qv0.z, a); bacc = fmaf(kv0.w, qv0.w, bacc);
    a = fmaf(kv1.x, qv1.x, a); bacc = fmaf(kv1.y, qv1.y, bacc);
    a = fmaf(kv1.z, qv1.z, a); bacc = fmaf(kv1.w, qv1.w, bacc);
    a = fmaf(kv2.x, qv2.x, a); bacc = fmaf(kv2.y, qv2.y, bacc);
    a = fmaf(kv2.z, qv2.z, a); bacc = fmaf(kv2.w, qv2.w, bacc);
    a = fmaf(kv3.x, qv3.x, a); bacc = fmaf(kv3.y, qv3.y, bacc);
    a = fmaf(kv3.z, qv3.z, a); bacc = fmaf(kv3.w, qv3.w, bacc);
    float acc = a + bacc;

    #pragma unroll
    for (int o = 16; o; o >>= 1) acc += __shfl_xor_sync(0xffffffffu, acc, o);
    if (lane == 0) g_scores[warp] = acc * 0.04419417382415922f;  // 1/sqrt(512)
}

// softmax over L per batch; writes contiguous g_s and strided weights[:, :, blk]
__global__ void softmax_kernel(float* __restrict__ wout, int blk) {
    int b = blockIdx.x;
    int t = threadIdx.x;            // 512 threads
    __shared__ float red[16];
    const float* sc = g_scores + b * NL;

    float e[NL / 512];
    float m = -INFINITY;
    #pragma unroll
    for (int i = 0; i < NL / 512; i++) {
        e[i] = sc[t + i * 512];
        m = fmaxf(m, e[i]);
    }
    #pragma unroll
    for (int o = 16; o; o >>= 1) m = fmaxf(m, __shfl_xor_sync(0xffffffffu, m, o));
    int w = t >> 5;
    if ((t & 31) == 0) red[w] = m;
    __syncthreads();
    if (t < 16) {
        float x = red[t];
        #pragma unroll
        for (int o = 8; o; o >>= 1) x = fmaxf(x, __shfl_xor_sync(0xffffu, x, o));
        if (t == 0) red[0] = x;
    }
    __syncthreads();
    m = red[0];
    __syncthreads();

    float sum = 0.f;
    #pragma unroll
    for (int i = 0; i < NL / 512; i++) {
        e[i] = expf(e[i] - m);
        sum += e[i];
    }
    float tot = block_sum_512(sum, red);
    float inv = 1.0f / tot;

    #pragma unroll
    for (int i = 0; i < NL / 512; i++) {
        int l = t + i * 512;
        float sv = e[i] * inv;
        g_s[b * NL + l] = sv;
        wout[((size_t)b * NL + l) * NBLK + blk] = sv;
    }
}

// partial A: one block per (l-chunk, b); 128 threads, float4 per thread
__global__ void apart_kernel(const float* __restrict__ v) {
    int c = blockIdx.x;     // 0..NCHUNK-1
    int b = blockIdx.y;     // 0..31
    int t = threadIdx.x;    // 0..127
    __shared__ float ss[LCHUNK];
    if (t < LCHUNK) ss[t] = g_s[b * NL + c * LCHUNK + t];
    __syncthreads();
    const float4* vp = reinterpret_cast<const float4*>(
        v + ((size_t)b * NL + (size_t)c * LCHUNK) * ND) + t;  // row stride ND/4=128
    float4 a0 = {0,0,0,0}, a1 = {0,0,0,0}, a2 = {0,0,0,0}, a3 = {0,0,0,0};
    #pragma unroll 4
    for (int l = 0; l < LCHUNK; l += 4) {
        float4 v0 = __ldcs(vp + (l + 0) * 128);
        float4 v1 = __ldcs(vp + (l + 1) * 128);
        float4 v2 = __ldcs(vp + (l + 2) * 128);
        float4 v3 = __ldcs(vp + (l + 3) * 128);
        float s0 = ss[l + 0], s1 = ss[l + 1], s2 = ss[l + 2], s3 = ss[l + 3];
        a0.x = fmaf(s0, v0.x, a0.x); a0.y = fmaf(s0, v0.y, a0.y);
        a0.z = fmaf(s0, v0.z, a0.z); a0.w = fmaf(s0, v0.w, a0.w);
        a1.x = fmaf(s1, v1.x, a1.x); a1.y = fmaf(s1, v1.y, a1.y);
        a1.z = fmaf(s1, v1.z, a1.z); a1.w = fmaf(s1, v1.w, a1.w);
        a2.x = fmaf(s2, v2.x, a2.x); a2.y = fmaf(s2, v2.y, a2.y);
        a2.z = fmaf(s2, v2.z, a2.z); a2.w = fmaf(s2, v2.w, a2.w);
        a3.x = fmaf(s3, v3.x, a3.x); a3.y = fmaf(s3, v3.y, a3.y);
        a3.z = fmaf(s3, v3.z, a3.z); a3.w = fmaf(s3, v3.w, a3.w);
    }
    float4 r;
    r.x = (a0.x + a1.x) + (a2.x + a3.x);
    r.y = (a0.y + a1.y) + (a2.y + a3.y);
    r.z = (a0.z + a1.z) + (a2.z + a3.z);
    r.w = (a0.w + a1.w) + (a2.w + a3.w);
    reinterpret_cast<float4*>(g_Apart + (b * NCHUNK + c) * ND)[t] = r;
}

// fused tail: reduce partials + residual + Norm1 + FF(relu) + FF2 + residual + Norm2
__global__ void tail_kernel(const float* __restrict__ W1, const float* __restrict__ b1,
                            const float* __restrict__ W2, const float* __restrict__ b2,
                            const float* __restrict__ al1, const float* __restrict__ bi1,
                            const float* __restrict__ al2, const float* __restrict__ bi2,
                            float* __restrict__ out, int blk, int write_out, int out_off) {
    int b = blockIdx.x;   // 32
    int d = threadIdx.x;  // 512
    __shared__ float red[16];
    __shared__ float sh_q[ND];
    __shared__ float sh_p[ND];     // FF1 partials (2 halves)
    __shared__ float sh_h[NDFF];

    // 1. A = sum partials, x = A + q
    float x = g_q[b * ND + d];
    #pragma unroll
    for (int c = 0; c < NCHUNK; c++) x += g_Apart[(b * NCHUNK + c) * ND + d];

    // 2. Norm1 (ddof=1, denom std+eps)
    float mu  = block_sum_512(x, red) * (1.0f / ND);
    float dev = x - mu;
    float var = block_sum_512(dev * dev, red) * (1.0f / (ND - 1));
    float qn1 = al1[blk * ND + d] * dev / (sqrtf(var) + FEPS) + bi1[blk * ND + d];
    sh_q[d] = qn1;
    __syncthreads();

    // 3. FF1: h = relu(q_ @ W1 + b1). 512 threads = (half, j); MLP 8.
    {
        int j    = d & (NDFF - 1);
        int half = d >> 8;
        const float* w  = W1 + (size_t)blk * ND * NDFF + (size_t)(half * 256) * NDFF + j;
        const float* xq = sh_q + half * 256;
        float c0 = 0.f, c1 = 0.f, c2 = 0.f, c3 = 0.f;
        float c4 = 0.f, c5 = 0.f, c6 = 0.f, c7 = 0.f;
        #pragma unroll 4
        for (int i = 0; i < 256; i += 8) {
            c0 = fmaf(xq[i + 0], __ldg(w + (i + 0) * NDFF), c0);
            c1 = fmaf(xq[i + 1], __ldg(w + (i + 1) * NDFF), c1);
            c2 = fmaf(xq[i + 2], __ldg(w + (i + 2) * NDFF), c2);
            c3 = fmaf(xq[i + 3], __ldg(w + (i + 3) * NDFF), c3);
            c4 = fmaf(xq[i + 4], __ldg(w + (i + 4) * NDFF), c4);
            c5 = fmaf(xq[i + 5], __ldg(w + (i + 5) * NDFF), c5);
            c6 = fmaf(xq[i + 6], __ldg(w + (i + 6) * NDFF), c6);
            c7 = fmaf(xq[i + 7], __ldg(w + (i + 7) * NDFF), c7);
        }
        sh_p[d] = ((c0 + c1) + (c2 + c3)) + ((c4 + c5) + (c6 + c7));
    }
    __syncthreads();
    if (d < NDFF) {
        float hv = sh_p[d] + sh_p[d + 256] + b1[blk * NDFF + d];
        sh_h[d] = fmaxf(hv, 0.f);
    }
    __syncthreads();

    // 4. FF2: ff = h @ W2 + b2 (512 threads, one output d each, MLP 8)
    float acc = b2[blk * ND + d];
    {
        const float* w2 = W2 + (size_t)blk * NDFF * ND + d;  // col d, stride ND
        float c0 = 0.f, c1 = 0.f, c2 = 0.f, c3 = 0.f;
        float c4 = 0.f, c5 = 0.f, c6 = 0.f, c7 = 0.f;
        #pragma unroll 4
        for (int j = 0; j < NDFF; j += 8) {
            c0 = fmaf(sh_h[j + 0], __ldg(w2 + (j + 0) * ND), c0);
            c1 = fmaf(sh_h[j + 1], __ldg(w2 + (j + 1) * ND), c1);
            c2 = fmaf(sh_h[j + 2], __ldg(w2 + (j + 2) * ND), c2);
            c3 = fmaf(sh_h[j + 3], __ldg(w2 + (j + 3) * ND), c3);
            c4 = fmaf(sh_h[j + 4], __ldg(w2 + (j + 4) * ND), c4);
            c5 = fmaf(sh_h[j + 5], __ldg(w2 + (j + 5) * ND), c5);
            c6 = fmaf(sh_h[j + 6], __ldg(w2 + (j + 6) * ND), c6);
            c7 = fmaf(sh_h[j + 7], __ldg(w2 + (j + 7) * ND), c7);
        }
        acc += ((c0 + c1) + (c2 + c3)) + ((c4 + c5) + (c6 + c7));
    }
    float x2 = qn1 + acc;

    // 5. Norm2
    float mu2  = block_sum_512(x2, red) * (1.0f / ND);
    float dev2 = x2 - mu2;
    float var2 = block_sum_512(dev2 * dev2, red) * (1.0f / (ND - 1));
    float qn2 = al2[blk * ND + d] * dev2 / (sqrtf(var2) + FEPS) + bi2[blk * ND + d];

    g_q[b * ND + d] = qn2;
    if (write_out) out[b * (2 * ND) + out_off + d] = qn2;
}

// ---------------- launch ----------------
extern "C" void kernel_launch(void* const* d_in, const int* in_sizes, int n_in,
                              void* d_out, int out_size) {
    const float* q   = (const float*)d_in[0];
    const float* k   = (const float*)d_in[1];
    const float* v   = (const float*)d_in[2];
    const float* W1  = (const float*)d_in[3];
    const float* b1  = (const float*)d_in[4];
    const float* W2  = (const float*)d_in[5];
    const float* b2  = (const float*)d_in[6];
    const float* al1 = (const float*)d_in[7];
    const float* bi1 = (const float*)d_in[8];
    const float* al2 = (const float*)d_in[9];
    const float* bi2 = (const float*)d_in[10];

    float* out_p = (float*)d_out;                 // (32, 1024)
    float* w_p   = (float*)d_out + NB * 2 * ND;   // (32, 2048, 6)

    initq_kernel<<<(NB * ND + 255) / 256, 256>>>(q);

    for (int blk = 0; blk < NBLK; blk++) {
        scores_kernel<<<(NB * NL * 32) / 256, 256>>>(k);
        softmax_kernel<<<NB, 512>>>(w_p, blk);
        apart_kernel<<<dim3(NCHUNK, NB), 128>>>(v);
        int wr = (blk == 2 || blk == 5) ? 1 : 0;
        int off = (blk == 5) ? ND : 0;
        tail_kernel<<<NB, ND>>>(W1, b1, W2, b2, al1, bi1, al2, bi2,
                                out_p, blk, wr, off);
    }
}